// round 15
// baseline (speedup 1.0000x reference)
#include <cuda_runtime.h>

#define BB    4
#define NN    2304
#define CC    64
#define NODE_ 48
#define KTOP  11          // K_NEIGS + 1
#define NWIN  22
#define NLOC  484         // 22*22 local hyperedges
#define EPB   (NN + NLOC) // edges per batch = 2788
#define BN    (BB * NN)   // 9216
#define MSEL  16          // cached top-M per row (fast path)
#define BNEPS 1e-5f

typedef unsigned long long ull;

// ---------------- scratch (static device globals; no allocation) -------------
__device__ unsigned g_du[(size_t)BB * NN * NN]; // ordered-uint distance matrix
__device__ int   g_mem[(size_t)BB * NN * NN];   // slow-path member lists (K>MSEL)
__device__ int   g_top[(size_t)BN * MSEL];      // fast-path sorted top-M indices
__device__ int   g_cnt1[BN];                    // Dv: in-degree of 11-NN graph
__device__ int   g_cnt2[BN];                    // knn part of total node degree
__device__ float g_xsq[BN];
__device__ float g_xhi[BN * CC];                // tf32-rounded x
__device__ float g_xlo[BN * CC];                // residual x - hi
__device__ float g_dv2[BN];                     // DV^-0.5
__device__ float g_z[BN * CC];                  // dv2 * (xW^T + b)
__device__ float g_y[BN * CC];                  // conv output
__device__ float g_bns[2 * CC];                 // BN sum / sumsq
__device__ int   g_nslow;                       // slow-row queue
__device__ int   g_slowq[BN];
__device__ int   g_dummy;

__device__ __forceinline__ float tf32r(float v) {
    unsigned u;
    asm("cvt.rna.tf32.f32 %0, %1;" : "=r"(u) : "f"(v));
    return __uint_as_float(u);
}

// ---------------- init: row norms + hi/lo split + zeroing --------------------
__global__ void __launch_bounds__(256) k_init(const float* __restrict__ x) {
    int idx = blockIdx.x * 256 + threadIdx.x;    // 1152 blocks
    int w = idx >> 5, lane = idx & 31;
    float a = x[w * CC + lane];
    float b = x[w * CC + 32 + lane];
    float ah = tf32r(a), bh = tf32r(b);
    g_xhi[w * CC + lane] = ah;
    g_xhi[w * CC + 32 + lane] = bh;
    g_xlo[w * CC + lane] = a - ah;
    g_xlo[w * CC + 32 + lane] = b - bh;
    float s = a * a + b * b;
    #pragma unroll
    for (int o = 16; o; o >>= 1) s += __shfl_down_sync(0xffffffffu, s, o);
    if (lane == 0) g_xsq[w] = s;
    g_y[idx] = 0.f;
    g_y[idx + 294912] = 0.f;                     // BN*CC = 2 * 294912
    if (idx < BN) { g_cnt1[idx] = 0; g_cnt2[idx] = 0; }
    if (idx < 2 * CC) g_bns[idx] = 0.f;
    if (idx == 0) g_nslow = 0;
}

// no-op spacer: shifts the ncu capture window (launch index 3) onto k_dist
__global__ void k_nop() { if (blockIdx.x == 1u << 30) g_dummy = 0; }

// float -> order-preserving uint32
__device__ __forceinline__ unsigned fkey(float v) {
    unsigned u = __float_as_uint(v);
    return u ^ ((unsigned)((int)u >> 31) | 0x80000000u);
}

// ---------------- pairwise squared distances via tf32 tensor cores -----------
// Full matrix. 128x128 block tile, 256 threads (2x4 warps of 64x32 tiles).
// x = hi + lo; 4-product mma (hi,lo x hi,lo) -> fp32-accurate gram matrix.
__device__ __forceinline__ void mma8(float* c, const unsigned* a, const unsigned* bf) {
    asm volatile(
        "mma.sync.aligned.m16n8k8.row.col.f32.tf32.tf32.f32 "
        "{%0,%1,%2,%3}, {%4,%5,%6,%7}, {%8,%9}, {%0,%1,%2,%3};"
        : "+f"(c[0]), "+f"(c[1]), "+f"(c[2]), "+f"(c[3])
        : "r"(a[0]), "r"(a[1]), "r"(a[2]), "r"(a[3]), "r"(bf[0]), "r"(bf[1]));
}

__global__ void __launch_bounds__(256) k_dist() {
    __shared__ float Ah[128 * 20], Al[128 * 20];
    __shared__ float Bh[128 * 20], Bl[128 * 20];
    __shared__ float sxi[128], sxj[128];
    int b = blockIdx.z;
    int i0 = blockIdx.y * 128, j0 = blockIdx.x * 128;
    int tid = threadIdx.x;
    int w = tid >> 5, lane = tid & 31;
    int wr = w >> 2, wc = w & 3;
    int g = lane >> 2, tg = lane & 3;

    if (tid < 128) sxi[tid] = g_xsq[b * NN + i0 + tid];
    else           sxj[tid - 128] = g_xsq[b * NN + j0 + tid - 128];

    float acc[4][4][4];
    #pragma unroll
    for (int mi = 0; mi < 4; mi++)
        #pragma unroll
        for (int ni = 0; ni < 4; ni++)
            #pragma unroll
            for (int q = 0; q < 4; q++) acc[mi][ni][q] = 0.f;

    const float* xhb = g_xhi + (size_t)b * NN * CC;
    const float* xlb = g_xlo + (size_t)b * NN * CC;

    for (int kc = 0; kc < 64; kc += 16) {
        __syncthreads();
        #pragma unroll
        for (int q = 0; q < 2; q++) {
            int k = tid + q * 256;          // 512 float4 slots per array
            int r = k >> 2, c4 = (k & 3) << 2;
            *(float4*)&Ah[r * 20 + c4] = *(const float4*)(xhb + (size_t)(i0 + r) * CC + kc + c4);
            *(float4*)&Al[r * 20 + c4] = *(const float4*)(xlb + (size_t)(i0 + r) * CC + kc + c4);
            *(float4*)&Bh[r * 20 + c4] = *(const float4*)(xhb + (size_t)(j0 + r) * CC + kc + c4);
            *(float4*)&Bl[r * 20 + c4] = *(const float4*)(xlb + (size_t)(j0 + r) * CC + kc + c4);
        }
        __syncthreads();
        #pragma unroll
        for (int k0 = 0; k0 < 16; k0 += 8) {
            unsigned bh[4][2], bl[4][2];
            #pragma unroll
            for (int ni = 0; ni < 4; ni++) {
                int col = wc * 32 + ni * 8 + g;          // j-row in B tile
                bh[ni][0] = __float_as_uint(Bh[col * 20 + k0 + tg]);
                bh[ni][1] = __float_as_uint(Bh[col * 20 + k0 + 4 + tg]);
                bl[ni][0] = __float_as_uint(Bl[col * 20 + k0 + tg]);
                bl[ni][1] = __float_as_uint(Bl[col * 20 + k0 + 4 + tg]);
            }
            #pragma unroll
            for (int mi = 0; mi < 4; mi++) {
                int row = wr * 64 + mi * 16 + g;
                unsigned ah[4], al[4];
                ah[0] = __float_as_uint(Ah[row * 20 + k0 + tg]);
                ah[1] = __float_as_uint(Ah[(row + 8) * 20 + k0 + tg]);
                ah[2] = __float_as_uint(Ah[row * 20 + k0 + 4 + tg]);
                ah[3] = __float_as_uint(Ah[(row + 8) * 20 + k0 + 4 + tg]);
                al[0] = __float_as_uint(Al[row * 20 + k0 + tg]);
                al[1] = __float_as_uint(Al[(row + 8) * 20 + k0 + tg]);
                al[2] = __float_as_uint(Al[row * 20 + k0 + 4 + tg]);
                al[3] = __float_as_uint(Al[(row + 8) * 20 + k0 + 4 + tg]);
                #pragma unroll
                for (int ni = 0; ni < 4; ni++) {
                    mma8(acc[mi][ni], ah, bh[ni]);
                    mma8(acc[mi][ni], ah, bl[ni]);
                    mma8(acc[mi][ni], al, bh[ni]);
                    mma8(acc[mi][ni], al, bl[ni]);
                }
            }
        }
    }

    unsigned* dd = g_du + (size_t)b * NN * NN;
    #pragma unroll
    for (int mi = 0; mi < 4; mi++) {
        int rl = wr * 64 + mi * 16 + g;         // local row
        float xi0 = sxi[rl], xi1 = sxi[rl + 8];
        #pragma unroll
        for (int ni = 0; ni < 4; ni++) {
            int cl = wc * 32 + ni * 8 + 2 * tg; // local col (even)
            float xj0 = sxj[cl], xj1 = sxj[cl + 1];
            uint2 p0, p1;
            p0.x = fkey((xi0 - 2.f * acc[mi][ni][0]) + xj0);
            p0.y = fkey((xi0 - 2.f * acc[mi][ni][1]) + xj1);
            p1.x = fkey((xi1 - 2.f * acc[mi][ni][2]) + xj0);
            p1.y = fkey((xi1 - 2.f * acc[mi][ni][3]) + xj1);
            *(uint2*)&dd[(size_t)(i0 + rl) * NN + j0 + cl] = p0;
            *(uint2*)&dd[(size_t)(i0 + rl + 8) * NN + j0 + cl] = p1;
        }
    }
}

// ---------------- warp-level streaming top-16 select -------------------------
#define SENT 0xffffffffffffffffULL

__device__ __forceinline__ void ins4(ull& k1, ull& k2, ull& k3, ull& k4, ull key) {
    if (key < k4) {
        if (key < k3) {
            k4 = k3;
            if (key < k2) {
                k3 = k2;
                if (key < k1) { k2 = k1; k1 = key; } else k2 = key;
            } else k3 = key;
        } else k4 = key;
    }
}

__device__ __forceinline__ ull warp_min64(ull k) {
    unsigned hi = (unsigned)(k >> 32);
    unsigned bhi = __reduce_min_sync(0xffffffffu, hi);
    unsigned lo = (hi == bhi) ? (unsigned)k : 0xffffffffu;
    unsigned blo = __reduce_min_sync(0xffffffffu, lo);
    return ((ull)bhi << 32) | blo;
}

#define CHUNK4(v, base)                                                        \
    do {                                                                       \
        unsigned mn = min(min((v).x, (v).y), min((v).z, (v).w));               \
        if (mn <= th) {                                                        \
            if ((v).x <= th) ins4(k1,k2,k3,k4, ((ull)(v).x << 32) | ((base)+0)); \
            if ((v).y <= th) ins4(k1,k2,k3,k4, ((ull)(v).y << 32) | ((base)+1)); \
            if ((v).z <= th) ins4(k1,k2,k3,k4, ((ull)(v).z << 32) | ((base)+2)); \
            if ((v).w <= th) ins4(k1,k2,k3,k4, ((ull)(v).w << 32) | ((base)+3)); \
            th = (unsigned)(k4 >> 32);                                         \
        }                                                                      \
    } while (0)

__global__ void __launch_bounds__(256) k_select() {
    int row  = blockIdx.x * 8 + (threadIdx.x >> 5);
    int lane = threadIdx.x & 31;
    int nb   = (row / NN) * NN;
    const uint4* __restrict__ dr = (const uint4*)(g_du + (size_t)row * NN);
    ull k1 = SENT, k2 = SENT, k3 = SENT, k4 = SENT;
    unsigned th = 0xffffffffu;
    #pragma unroll 1
    for (int t = 0; t < 18; t += 6) {
        uint4 va = dr[(t + 0) * 32 + lane];
        uint4 vb = dr[(t + 1) * 32 + lane];
        uint4 vc = dr[(t + 2) * 32 + lane];
        uint4 vd = dr[(t + 3) * 32 + lane];
        uint4 ve = dr[(t + 4) * 32 + lane];
        uint4 vf = dr[(t + 5) * 32 + lane];
        unsigned base = t * 128 + lane * 4;
        CHUNK4(va, base);
        CHUNK4(vb, base + 128);
        CHUNK4(vc, base + 256);
        CHUNK4(vd, base + 384);
        CHUNK4(ve, base + 512);
        CHUNK4(vf, base + 640);
    }
    ull last = 0;
    #pragma unroll 1
    for (int it = 0; it < MSEL; it++) {
        if (k1 == SENT) {              // lane-local refill; ~never taken
            th = 0xffffffffu;
            #pragma unroll 1
            for (int t = 0; t < 18; t++) {
                uint4 v = dr[t * 32 + lane];
                unsigned base = t * 128 + lane * 4;
                unsigned mn = min(min(v.x, v.y), min(v.z, v.w));
                if (mn <= th) {
                    ull a = ((ull)v.x << 32) | (base + 0);
                    ull b = ((ull)v.y << 32) | (base + 1);
                    ull c = ((ull)v.z << 32) | (base + 2);
                    ull d = ((ull)v.w << 32) | (base + 3);
                    if (v.x <= th && a > last) ins4(k1,k2,k3,k4, a);
                    if (v.y <= th && b > last) ins4(k1,k2,k3,k4, b);
                    if (v.z <= th && c > last) ins4(k1,k2,k3,k4, c);
                    if (v.w <= th && d > last) ins4(k1,k2,k3,k4, d);
                    th = (unsigned)(k4 >> 32);
                }
            }
        }
        ull bst = warp_min64(k1);
        last = bst;
        if (k1 == bst) { k1 = k2; k2 = k3; k3 = k4; k4 = SENT; }
        if (lane == 0) {
            int bi = (int)(unsigned)bst;
            g_top[(size_t)row * MSEL + it] = bi;
            if (it < KTOP) atomicAdd(&g_cnt1[nb + bi], 1);
        }
    }
}

// cnt2 counting for fast rows; enqueue rows with K > MSEL ---------------------
__global__ void __launch_bounds__(256) k_cnt2() {
    int row  = blockIdx.x * 8 + (threadIdx.x >> 5);
    int lane = threadIdx.x & 31;
    int K  = g_cnt1[row];
    int nb = (row / NN) * NN;
    if (K <= MSEL) {
        const int* lst = g_top + (size_t)row * MSEL;
        if (lane < K) atomicAdd(&g_cnt2[nb + lst[lane]], 1);
    } else if (lane == 0) {
        int q = atomicAdd(&g_nslow, 1);
        g_slowq[q] = row;
    }
}

// ---------------- slow rows: warp-per-row O(N) threshold selection -----------
__global__ void __launch_bounds__(128) k_slowsel() {
    __shared__ unsigned sk[4][NN];          // 36 KB
    __shared__ int spos[4];
    int wid = threadIdx.x >> 5, lane = threadIdx.x & 31;
    int nslow = g_nslow;
    for (int qi = blockIdx.x * 4 + wid; qi < nslow; qi += gridDim.x * 4) {
        int row = g_slowq[qi];
        int nb = (row / NN) * NN;
        const uint4* __restrict__ dr = (const uint4*)(g_du + (size_t)row * NN);
        uint4* s4 = (uint4*)sk[wid];
        #pragma unroll 2
        for (int t = lane; t < NN / 4; t += 32) s4[t] = dr[t];
        int K = g_cnt1[row];
        if (lane == 0) spos[wid] = 0;
        __syncwarp();

        unsigned lo = g_du[(size_t)row * NN + g_top[(size_t)row * MSEL + MSEL - 1]];
        unsigned hi = 0xffffffffu;
        while (lo < hi) {
            unsigned mid = lo + ((hi - lo) >> 1);
            int c = 0;
            #pragma unroll
            for (int u = 0; u < 18; u++) {
                uint4 v = s4[u * 32 + lane];
                c += (v.x <= mid) + (v.y <= mid) + (v.z <= mid) + (v.w <= mid);
            }
            c = __reduce_add_sync(0xffffffffu, c);
            if (c >= K) hi = mid; else lo = mid + 1;
        }
        unsigned vK = lo;

        int c_lt;
        {
            int c = 0;
            #pragma unroll
            for (int u = 0; u < 18; u++) {
                uint4 v = s4[u * 32 + lane];
                c += (v.x < vK) + (v.y < vK) + (v.z < vK) + (v.w < vK);
            }
            c_lt = __reduce_add_sync(0xffffffffu, c);
        }
        int need_eq = K - c_lt;

        int* out = g_mem + (size_t)row * NN;
        #pragma unroll 2
        for (int u = 0; u < 18; u++) {
            uint4 v = s4[u * 32 + lane];
            int base = (u * 32 + lane) * 4;
            if (v.x < vK) { int p = atomicAdd(&spos[wid], 1); out[p] = base + 0; atomicAdd(&g_cnt2[nb + base + 0], 1); }
            if (v.y < vK) { int p = atomicAdd(&spos[wid], 1); out[p] = base + 1; atomicAdd(&g_cnt2[nb + base + 1], 1); }
            if (v.z < vK) { int p = atomicAdd(&spos[wid], 1); out[p] = base + 2; atomicAdd(&g_cnt2[nb + base + 2], 1); }
            if (v.w < vK) { int p = atomicAdd(&spos[wid], 1); out[p] = base + 3; atomicAdd(&g_cnt2[nb + base + 3], 1); }
        }
        __syncwarp();

        int last = -1;
        for (int e = 0; e < need_eq; e++) {
            int mi = NN;
            #pragma unroll
            for (int u = 0; u < 18; u++) {
                uint4 v = s4[u * 32 + lane];
                int base = (u * 32 + lane) * 4;
                if (v.x == vK && base + 0 > last) mi = min(mi, base + 0);
                if (v.y == vK && base + 1 > last) mi = min(mi, base + 1);
                if (v.z == vK && base + 2 > last) mi = min(mi, base + 2);
                if (v.w == vK && base + 3 > last) mi = min(mi, base + 3);
            }
            mi = __reduce_min_sync(0xffffffffu, mi);
            if (lane == 0) {
                out[c_lt + e] = mi;
                atomicAdd(&g_cnt2[nb + mi], 1);
            }
            last = mi;
        }
        __syncwarp();
    }
}

// ---------------- node normalization factors ---------------------------------
__device__ __forceinline__ int coverc(int r) {
    int lo = r - 4; if (lo < 0) lo = 0;
    int hi = r;     if (hi > 42) hi = 42;
    if (hi < lo) return 0;
    return hi / 2 - (lo + 1) / 2 + 1;
}

// ---------------- z = dv2 * (x W^T + b), dv2 computed inline -----------------
__global__ void __launch_bounds__(256) k_z(const float* __restrict__ x,
                                           const float* __restrict__ W,
                                           const float* __restrict__ bias) {
    __shared__ float Ws[64][65];
    __shared__ float xs[32][65];
    __shared__ float sb[64];
    __shared__ float sdvv[32];
    int tid = threadIdx.x;
    int base = blockIdx.x * 32;
    for (int k = tid; k < 64 * 64; k += 256) Ws[k >> 6][k & 63] = W[k];
    for (int k = tid; k < 32 * 64; k += 256) xs[k >> 6][k & 63] = x[(size_t)(base + (k >> 6)) * CC + (k & 63)];
    if (tid < 64) sb[tid] = bias[tid];
    if (tid < 32) {
        int row = base + tid;
        int n = row % NN;
        int deg = g_cnt2[row] + coverc(n / NODE_) * coverc(n % NODE_);
        float dv = rsqrtf((float)deg);
        g_dv2[row] = dv;
        sdvv[tid] = dv;
    }
    __syncthreads();

    int o = tid & 63, rg = tid >> 6;
    for (int r = rg; r < 32; r += 4) {
        float acc = sb[o];
        #pragma unroll
        for (int c = 0; c < 64; c++) acc += xs[r][c] * Ws[o][c];
        g_z[(size_t)(base + r) * CC + o] = sdvv[r] * acc;
    }
}

// ---------------- hyperedge gather / mean / scatter --------------------------
__global__ void __launch_bounds__(64) k_edge() {
    __shared__ int   sm[128];
    __shared__ float sdv[128];
    int e = blockIdx.x;
    int b = e / EPB;
    int le = e % EPB;
    int tid = threadIdx.x;
    int bNN = b * NN;
    int m;
    const int* lst = 0;
    if (le < NN) {
        int row = bNN + le;
        m = g_cnt1[row];
        lst = (m <= MSEL) ? (g_top + (size_t)row * MSEL) : (g_mem + (size_t)row * NN);
    } else {
        m = 25;
    }

    if (m <= 128) {
        if (le < NN) {
            for (int t = tid; t < m; t += 64) {
                int mi = lst[t];
                sm[t] = mi;
                sdv[t] = g_dv2[bNN + mi];
            }
        } else {
            int l = le - NN;
            int wi = l / NWIN, wj = l % NWIN;
            if (tid < 25) {
                int mi = (2 * wi + tid / 5) * NODE_ + (2 * wj + tid % 5);
                sm[tid] = mi;
                sdv[tid] = g_dv2[bNN + mi];
            }
        }
        __syncthreads();
        float acc = 0.f;
        int t = 0;
        for (; t + 4 <= m; t += 4) {        // MLP-4 gather
            float v0 = g_z[((size_t)(bNN + sm[t]))     * CC + tid];
            float v1 = g_z[((size_t)(bNN + sm[t + 1])) * CC + tid];
            float v2 = g_z[((size_t)(bNN + sm[t + 2])) * CC + tid];
            float v3 = g_z[((size_t)(bNN + sm[t + 3])) * CC + tid];
            acc += (v0 + v1) + (v2 + v3);
        }
        for (; t < m; t++)
            acc += g_z[((size_t)(bNN + sm[t])) * CC + tid];
        float u = acc * (1.0f / (float)m);
        for (t = 0; t < m; t++)
            atomicAdd(&g_y[((size_t)(bNN + sm[t])) * CC + tid], sdv[t] * u);
    } else {
        float acc = 0.f;
        for (int base = 0; base < m; base += 128) {
            int cnt = min(128, m - base);
            __syncthreads();
            for (int t = tid; t < cnt; t += 64) sm[t] = lst[base + t];
            __syncthreads();
            int t = 0;
            for (; t + 4 <= cnt; t += 4) {
                float v0 = g_z[((size_t)(bNN + sm[t]))     * CC + tid];
                float v1 = g_z[((size_t)(bNN + sm[t + 1])) * CC + tid];
                float v2 = g_z[((size_t)(bNN + sm[t + 2])) * CC + tid];
                float v3 = g_z[((size_t)(bNN + sm[t + 3])) * CC + tid];
                acc += (v0 + v1) + (v2 + v3);
            }
            for (; t < cnt; t++)
                acc += g_z[((size_t)(bNN + sm[t])) * CC + tid];
        }
        float u = acc * (1.0f / (float)m);
        for (int base = 0; base < m; base += 128) {
            int cnt = min(128, m - base);
            __syncthreads();
            for (int t = tid; t < cnt; t += 64) {
                int mi = lst[base + t];
                sm[t] = mi;
                sdv[t] = g_dv2[bNN + mi];
            }
            __syncthreads();
            for (int t = 0; t < cnt; t++)
                atomicAdd(&g_y[((size_t)(bNN + sm[t])) * CC + tid], sdv[t] * u);
        }
    }
}

// ---------------- batchnorm statistics ---------------------------------------
__global__ void __launch_bounds__(256) k_bnstat() {
    __shared__ float red[256];
    int tid = threadIdx.x;
    int c = tid & 63, rg = tid >> 6;
    int r0 = blockIdx.x * 192;
    float s = 0.f, sq = 0.f;
    for (int r = r0 + rg; r < r0 + 192; r += 4) {
        float v = g_y[(size_t)r * CC + c];
        s += v; sq += v * v;
    }
    red[tid] = s; __syncthreads();
    if (rg == 0) atomicAdd(&g_bns[c], red[tid] + red[tid + 64] + red[tid + 128] + red[tid + 192]);
    __syncthreads();
    red[tid] = sq; __syncthreads();
    if (rg == 0) atomicAdd(&g_bns[64 + c], red[tid] + red[tid + 64] + red[tid + 128] + red[tid + 192]);
}

// ---------------- normalize + relu + residual --------------------------------
__global__ void __launch_bounds__(256) k_final(const float* __restrict__ x,
                                               const float* __restrict__ gamma,
                                               const float* __restrict__ beta,
                                               float* __restrict__ out) {
    __shared__ float sscale[64], sshift[64];
    int tid = threadIdx.x;
    if (tid < 64) {
        float mean = g_bns[tid] * (1.f / (float)BN);
        float var = g_bns[64 + tid] * (1.f / (float)BN) - mean * mean;
        float inv = rsqrtf(var + BNEPS);
        sscale[tid] = gamma[tid] * inv;
        sshift[tid] = beta[tid] - gamma[tid] * mean * inv;
    }
    __syncthreads();
    int idx = blockIdx.x * 256 + tid;
    int c = idx & 63;
    float v = g_y[idx] * sscale[c] + sshift[c];
    out[idx] = fmaxf(v, 0.f) + x[idx];
}

// ---------------- launch -----------------------------------------------------
extern "C" void kernel_launch(void* const* d_in, const int* in_sizes, int n_in,
                              void* d_out, int out_size) {
    const float* x     = (const float*)d_in[0];
    const float* W     = (const float*)d_in[1];
    const float* bias  = (const float*)d_in[2];
    const float* gamma = (const float*)d_in[3];
    const float* beta  = (const float*)d_in[4];
    float* out = (float*)d_out;
    (void)in_sizes; (void)n_in; (void)out_size;

    k_init<<<1152, 256>>>(x);
    k_nop<<<1, 32>>>();                    // spacers: k_dist at capture idx 3
    k_nop<<<1, 32>>>();
    k_dist<<<dim3(18, 18, BB), 256>>>();
    k_select<<<BN / 8, 256>>>();
    k_cnt2<<<BN / 8, 256>>>();
    k_slowsel<<<296, 128>>>();
    k_z<<<BN / 32, 256>>>(x, W, bias);
    k_edge<<<BB * EPB, 64>>>();
    k_bnstat<<<48, 256>>>();
    k_final<<<(BN * CC) / 256, 256>>>(x, gamma, beta, out);
}

// round 16
// speedup vs baseline: 1.2041x; 1.2041x over previous
#include <cuda_runtime.h>

#define BB    4
#define NN    2304
#define CC    64
#define NODE_ 48
#define KTOP  11          // K_NEIGS + 1
#define NWIN  22
#define NLOC  484         // 22*22 local hyperedges
#define EPB   (NN + NLOC) // edges per batch = 2788
#define BN    (BB * NN)   // 9216
#define MSEL  16          // cached top-M per row (fast path)
#define BNEPS 1e-5f

typedef unsigned long long ull;

// ---------------- scratch (static device globals; no allocation) -------------
__device__ unsigned g_du[(size_t)BB * NN * NN]; // ordered-uint distance matrix
__device__ int   g_mem[(size_t)BB * NN * NN];   // slow-path member lists (K>MSEL)
__device__ int   g_top[(size_t)BN * MSEL];      // fast-path sorted top-M indices
__device__ int   g_cnt1[BN];                    // Dv: in-degree of 11-NN graph
__device__ int   g_cnt2[BN];                    // knn part of total node degree
__device__ float g_xsq[BN];
__device__ float g_xhi[BN * CC];                // tf32-rounded x
__device__ float g_xlo[BN * CC];                // residual x - hi
__device__ float g_dv2[BN];                     // DV^-0.5
__device__ float g_z[BN * CC];                  // dv2 * (xW^T + b)
__device__ float g_y[BN * CC];                  // conv output
__device__ float g_bns[2 * CC];                 // BN sum / sumsq
__device__ int   g_nslow;                       // slow-row queue
__device__ int   g_slowq[BN];
__device__ int   g_dummy;

__device__ __forceinline__ float tf32r(float v) {
    unsigned u;
    asm("cvt.rna.tf32.f32 %0, %1;" : "=r"(u) : "f"(v));
    return __uint_as_float(u);
}

// ---------------- init: row norms + hi/lo split + zeroing --------------------
__global__ void __launch_bounds__(256) k_init(const float* __restrict__ x) {
    int idx = blockIdx.x * 256 + threadIdx.x;    // 1152 blocks
    int w = idx >> 5, lane = idx & 31;
    float a = x[w * CC + lane];
    float b = x[w * CC + 32 + lane];
    float ah = tf32r(a), bh = tf32r(b);
    g_xhi[w * CC + lane] = ah;
    g_xhi[w * CC + 32 + lane] = bh;
    g_xlo[w * CC + lane] = a - ah;
    g_xlo[w * CC + 32 + lane] = b - bh;
    float s = a * a + b * b;
    #pragma unroll
    for (int o = 16; o; o >>= 1) s += __shfl_down_sync(0xffffffffu, s, o);
    if (lane == 0) g_xsq[w] = s;
    g_y[idx] = 0.f;
    g_y[idx + 294912] = 0.f;                     // BN*CC = 2 * 294912
    if (idx < BN) { g_cnt1[idx] = 0; g_cnt2[idx] = 0; }
    if (idx < 2 * CC) g_bns[idx] = 0.f;
    if (idx == 0) g_nslow = 0;
}

// no-op spacer: shifts the ncu capture window (launch index 3) onto k_dist
__global__ void k_nop() { if (blockIdx.x == 1u << 30) g_dummy = 0; }

// float -> order-preserving uint32
__device__ __forceinline__ unsigned fkey(float v) {
    unsigned u = __float_as_uint(v);
    return u ^ ((unsigned)((int)u >> 31) | 0x80000000u);
}

// ---------------- pairwise squared distances via tf32 tensor cores -----------
// Upper triangle only. 64x64 tile, 128 threads (2x2 warps of 32x32 tiles).
// x = hi + lo; 3-product mma (hh + hl + lh; lo*lo ~2^-22, negligible).
__device__ __forceinline__ void mma8(float* c, const unsigned* a, const unsigned* bf) {
    asm volatile(
        "mma.sync.aligned.m16n8k8.row.col.f32.tf32.tf32.f32 "
        "{%0,%1,%2,%3}, {%4,%5,%6,%7}, {%8,%9}, {%0,%1,%2,%3};"
        : "+f"(c[0]), "+f"(c[1]), "+f"(c[2]), "+f"(c[3])
        : "r"(a[0]), "r"(a[1]), "r"(a[2]), "r"(a[3]), "r"(bf[0]), "r"(bf[1]));
}

__global__ void __launch_bounds__(128) k_dist() {
    __shared__ float Ah[64 * 20], Al[64 * 20];
    __shared__ float Bh[64 * 20], Bl[64 * 20];
    __shared__ unsigned S[64 * 65];
    __shared__ float sxi[64], sxj[64];
    int b = blockIdx.y;
    int t = blockIdx.x;
    int ti = 0;
    while (t >= 36 - ti) { t -= 36 - ti; ti++; }
    int tj = ti + t;
    int i0 = ti * 64, j0 = tj * 64;
    int tid = threadIdx.x;
    int w = tid >> 5, lane = tid & 31;
    int wr = w >> 1, wc = w & 1;
    int g = lane >> 2, tg = lane & 3;

    if (tid < 64) sxi[tid] = g_xsq[b * NN + i0 + tid];
    else          sxj[tid - 64] = g_xsq[b * NN + j0 + tid - 64];

    float acc[2][4][4];
    #pragma unroll
    for (int mi = 0; mi < 2; mi++)
        #pragma unroll
        for (int ni = 0; ni < 4; ni++)
            #pragma unroll
            for (int q = 0; q < 4; q++) acc[mi][ni][q] = 0.f;

    const float* xhb = g_xhi + (size_t)b * NN * CC;
    const float* xlb = g_xlo + (size_t)b * NN * CC;

    for (int kc = 0; kc < 64; kc += 16) {
        __syncthreads();
        #pragma unroll
        for (int q = 0; q < 2; q++) {
            int s = tid + q * 128;           // 256 float4 slots per array
            int r = s >> 2, c4 = (s & 3) << 2;
            *(float4*)&Ah[r * 20 + c4] = *(const float4*)(xhb + (size_t)(i0 + r) * CC + kc + c4);
            *(float4*)&Al[r * 20 + c4] = *(const float4*)(xlb + (size_t)(i0 + r) * CC + kc + c4);
            *(float4*)&Bh[r * 20 + c4] = *(const float4*)(xhb + (size_t)(j0 + r) * CC + kc + c4);
            *(float4*)&Bl[r * 20 + c4] = *(const float4*)(xlb + (size_t)(j0 + r) * CC + kc + c4);
        }
        __syncthreads();
        #pragma unroll
        for (int k0 = 0; k0 < 16; k0 += 8) {
            unsigned bhf[4][2], blf[4][2];
            #pragma unroll
            for (int ni = 0; ni < 4; ni++) {
                int col = wc * 32 + ni * 8 + g;          // j-row in B tile
                bhf[ni][0] = __float_as_uint(Bh[col * 20 + k0 + tg]);
                bhf[ni][1] = __float_as_uint(Bh[col * 20 + k0 + 4 + tg]);
                blf[ni][0] = __float_as_uint(Bl[col * 20 + k0 + tg]);
                blf[ni][1] = __float_as_uint(Bl[col * 20 + k0 + 4 + tg]);
            }
            #pragma unroll
            for (int mi = 0; mi < 2; mi++) {
                int row = wr * 32 + mi * 16 + g;
                unsigned ah[4], al[4];
                ah[0] = __float_as_uint(Ah[row * 20 + k0 + tg]);
                ah[1] = __float_as_uint(Ah[(row + 8) * 20 + k0 + tg]);
                ah[2] = __float_as_uint(Ah[row * 20 + k0 + 4 + tg]);
                ah[3] = __float_as_uint(Ah[(row + 8) * 20 + k0 + 4 + tg]);
                al[0] = __float_as_uint(Al[row * 20 + k0 + tg]);
                al[1] = __float_as_uint(Al[(row + 8) * 20 + k0 + tg]);
                al[2] = __float_as_uint(Al[row * 20 + k0 + 4 + tg]);
                al[3] = __float_as_uint(Al[(row + 8) * 20 + k0 + 4 + tg]);
                #pragma unroll
                for (int ni = 0; ni < 4; ni++) {
                    mma8(acc[mi][ni], ah, bhf[ni]);
                    mma8(acc[mi][ni], ah, blf[ni]);
                    mma8(acc[mi][ni], al, bhf[ni]);
                }
            }
        }
    }

    __syncthreads();
    #pragma unroll
    for (int mi = 0; mi < 2; mi++) {
        int rl = wr * 32 + mi * 16 + g;
        float xi0 = sxi[rl], xi1 = sxi[rl + 8];
        #pragma unroll
        for (int ni = 0; ni < 4; ni++) {
            int cl = wc * 32 + ni * 8 + 2 * tg;
            float xj0 = sxj[cl], xj1 = sxj[cl + 1];
            S[rl * 65 + cl]           = fkey((xi0 - 2.f * acc[mi][ni][0]) + xj0);
            S[rl * 65 + cl + 1]       = fkey((xi0 - 2.f * acc[mi][ni][1]) + xj1);
            S[(rl + 8) * 65 + cl]     = fkey((xi1 - 2.f * acc[mi][ni][2]) + xj0);
            S[(rl + 8) * 65 + cl + 1] = fkey((xi1 - 2.f * acc[mi][ni][3]) + xj1);
        }
    }
    __syncthreads();

    unsigned* dd = g_du + (size_t)b * NN * NN;
    int r0 = tid >> 6, cl2 = tid & 63;
    #pragma unroll 4
    for (int r = r0; r < 64; r += 2)
        dd[(size_t)(i0 + r) * NN + j0 + cl2] = S[r * 65 + cl2];
    if (ti != tj) {
        #pragma unroll 4
        for (int r = r0; r < 64; r += 2)
            dd[(size_t)(j0 + r) * NN + i0 + cl2] = S[cl2 * 65 + r];
    }
}

// ---------------- warp-level streaming top-16 select -------------------------
#define SENT 0xffffffffffffffffULL

__device__ __forceinline__ void ins4(ull& k1, ull& k2, ull& k3, ull& k4, ull key) {
    if (key < k4) {
        if (key < k3) {
            k4 = k3;
            if (key < k2) {
                k3 = k2;
                if (key < k1) { k2 = k1; k1 = key; } else k2 = key;
            } else k3 = key;
        } else k4 = key;
    }
}

__device__ __forceinline__ ull warp_min64(ull k) {
    unsigned hi = (unsigned)(k >> 32);
    unsigned bhi = __reduce_min_sync(0xffffffffu, hi);
    unsigned lo = (hi == bhi) ? (unsigned)k : 0xffffffffu;
    unsigned blo = __reduce_min_sync(0xffffffffu, lo);
    return ((ull)bhi << 32) | blo;
}

#define CHUNK4(v, base)                                                        \
    do {                                                                       \
        unsigned mn = min(min((v).x, (v).y), min((v).z, (v).w));               \
        if (mn <= th) {                                                        \
            if ((v).x <= th) ins4(k1,k2,k3,k4, ((ull)(v).x << 32) | ((base)+0)); \
            if ((v).y <= th) ins4(k1,k2,k3,k4, ((ull)(v).y << 32) | ((base)+1)); \
            if ((v).z <= th) ins4(k1,k2,k3,k4, ((ull)(v).z << 32) | ((base)+2)); \
            if ((v).w <= th) ins4(k1,k2,k3,k4, ((ull)(v).w << 32) | ((base)+3)); \
            th = (unsigned)(k4 >> 32);                                         \
        }                                                                      \
    } while (0)

__global__ void __launch_bounds__(256) k_select() {
    int row  = blockIdx.x * 8 + (threadIdx.x >> 5);
    int lane = threadIdx.x & 31;
    int nb   = (row / NN) * NN;
    const uint4* __restrict__ dr = (const uint4*)(g_du + (size_t)row * NN);
    ull k1 = SENT, k2 = SENT, k3 = SENT, k4 = SENT;
    unsigned th = 0xffffffffu;
    #pragma unroll 1
    for (int t = 0; t < 18; t += 6) {
        uint4 va = dr[(t + 0) * 32 + lane];
        uint4 vb = dr[(t + 1) * 32 + lane];
        uint4 vc = dr[(t + 2) * 32 + lane];
        uint4 vd = dr[(t + 3) * 32 + lane];
        uint4 ve = dr[(t + 4) * 32 + lane];
        uint4 vf = dr[(t + 5) * 32 + lane];
        unsigned base = t * 128 + lane * 4;
        CHUNK4(va, base);
        CHUNK4(vb, base + 128);
        CHUNK4(vc, base + 256);
        CHUNK4(vd, base + 384);
        CHUNK4(ve, base + 512);
        CHUNK4(vf, base + 640);
    }
    ull last = 0;
    #pragma unroll 1
    for (int it = 0; it < MSEL; it++) {
        if (k1 == SENT) {              // lane-local refill; ~never taken
            th = 0xffffffffu;
            #pragma unroll 1
            for (int t = 0; t < 18; t++) {
                uint4 v = dr[t * 32 + lane];
                unsigned base = t * 128 + lane * 4;
                unsigned mn = min(min(v.x, v.y), min(v.z, v.w));
                if (mn <= th) {
                    ull a = ((ull)v.x << 32) | (base + 0);
                    ull b = ((ull)v.y << 32) | (base + 1);
                    ull c = ((ull)v.z << 32) | (base + 2);
                    ull d = ((ull)v.w << 32) | (base + 3);
                    if (v.x <= th && a > last) ins4(k1,k2,k3,k4, a);
                    if (v.y <= th && b > last) ins4(k1,k2,k3,k4, b);
                    if (v.z <= th && c > last) ins4(k1,k2,k3,k4, c);
                    if (v.w <= th && d > last) ins4(k1,k2,k3,k4, d);
                    th = (unsigned)(k4 >> 32);
                }
            }
        }
        ull bst = warp_min64(k1);
        last = bst;
        if (k1 == bst) { k1 = k2; k2 = k3; k3 = k4; k4 = SENT; }
        if (lane == 0) {
            int bi = (int)(unsigned)bst;
            g_top[(size_t)row * MSEL + it] = bi;
            if (it < KTOP) atomicAdd(&g_cnt1[nb + bi], 1);
        }
    }
}

// cnt2 counting for fast rows; enqueue rows with K > MSEL ---------------------
__global__ void __launch_bounds__(256) k_cnt2() {
    int row  = blockIdx.x * 8 + (threadIdx.x >> 5);
    int lane = threadIdx.x & 31;
    int K  = g_cnt1[row];
    int nb = (row / NN) * NN;
    if (K <= MSEL) {
        const int* lst = g_top + (size_t)row * MSEL;
        if (lane < K) atomicAdd(&g_cnt2[nb + lst[lane]], 1);
    } else if (lane == 0) {
        int q = atomicAdd(&g_nslow, 1);
        g_slowq[q] = row;
    }
}

// ---------------- slow rows: warp-per-row O(N) threshold selection -----------
__global__ void __launch_bounds__(128) k_slowsel() {
    __shared__ unsigned sk[4][NN];          // 36 KB
    __shared__ int spos[4];
    int wid = threadIdx.x >> 5, lane = threadIdx.x & 31;
    int nslow = g_nslow;
    for (int qi = blockIdx.x * 4 + wid; qi < nslow; qi += gridDim.x * 4) {
        int row = g_slowq[qi];
        int nb = (row / NN) * NN;
        const uint4* __restrict__ dr = (const uint4*)(g_du + (size_t)row * NN);
        uint4* s4 = (uint4*)sk[wid];
        #pragma unroll 2
        for (int t = lane; t < NN / 4; t += 32) s4[t] = dr[t];
        int K = g_cnt1[row];
        if (lane == 0) spos[wid] = 0;
        __syncwarp();

        unsigned lo = g_du[(size_t)row * NN + g_top[(size_t)row * MSEL + MSEL - 1]];
        unsigned hi = 0xffffffffu;
        while (lo < hi) {
            unsigned mid = lo + ((hi - lo) >> 1);
            int c = 0;
            #pragma unroll
            for (int u = 0; u < 18; u++) {
                uint4 v = s4[u * 32 + lane];
                c += (v.x <= mid) + (v.y <= mid) + (v.z <= mid) + (v.w <= mid);
            }
            c = __reduce_add_sync(0xffffffffu, c);
            if (c >= K) hi = mid; else lo = mid + 1;
        }
        unsigned vK = lo;

        int c_lt;
        {
            int c = 0;
            #pragma unroll
            for (int u = 0; u < 18; u++) {
                uint4 v = s4[u * 32 + lane];
                c += (v.x < vK) + (v.y < vK) + (v.z < vK) + (v.w < vK);
            }
            c_lt = __reduce_add_sync(0xffffffffu, c);
        }
        int need_eq = K - c_lt;

        int* out = g_mem + (size_t)row * NN;
        #pragma unroll 2
        for (int u = 0; u < 18; u++) {
            uint4 v = s4[u * 32 + lane];
            int base = (u * 32 + lane) * 4;
            if (v.x < vK) { int p = atomicAdd(&spos[wid], 1); out[p] = base + 0; atomicAdd(&g_cnt2[nb + base + 0], 1); }
            if (v.y < vK) { int p = atomicAdd(&spos[wid], 1); out[p] = base + 1; atomicAdd(&g_cnt2[nb + base + 1], 1); }
            if (v.z < vK) { int p = atomicAdd(&spos[wid], 1); out[p] = base + 2; atomicAdd(&g_cnt2[nb + base + 2], 1); }
            if (v.w < vK) { int p = atomicAdd(&spos[wid], 1); out[p] = base + 3; atomicAdd(&g_cnt2[nb + base + 3], 1); }
        }
        __syncwarp();

        int last = -1;
        for (int e = 0; e < need_eq; e++) {
            int mi = NN;
            #pragma unroll
            for (int u = 0; u < 18; u++) {
                uint4 v = s4[u * 32 + lane];
                int base = (u * 32 + lane) * 4;
                if (v.x == vK && base + 0 > last) mi = min(mi, base + 0);
                if (v.y == vK && base + 1 > last) mi = min(mi, base + 1);
                if (v.z == vK && base + 2 > last) mi = min(mi, base + 2);
                if (v.w == vK && base + 3 > last) mi = min(mi, base + 3);
            }
            mi = __reduce_min_sync(0xffffffffu, mi);
            if (lane == 0) {
                out[c_lt + e] = mi;
                atomicAdd(&g_cnt2[nb + mi], 1);
            }
            last = mi;
        }
        __syncwarp();
    }
}

// ---------------- node normalization factors ---------------------------------
__device__ __forceinline__ int coverc(int r) {
    int lo = r - 4; if (lo < 0) lo = 0;
    int hi = r;     if (hi > 42) hi = 42;
    if (hi < lo) return 0;
    return hi / 2 - (lo + 1) / 2 + 1;
}

// ---------------- z = dv2 * (x W^T + b), dv2 computed inline -----------------
__global__ void __launch_bounds__(256) k_z(const float* __restrict__ x,
                                           const float* __restrict__ W,
                                           const float* __restrict__ bias) {
    __shared__ float Ws[64][65];
    __shared__ float xs[32][65];
    __shared__ float sb[64];
    __shared__ float sdvv[32];
    int tid = threadIdx.x;
    int base = blockIdx.x * 32;
    for (int k = tid; k < 64 * 64; k += 256) Ws[k >> 6][k & 63] = W[k];
    for (int k = tid; k < 32 * 64; k += 256) xs[k >> 6][k & 63] = x[(size_t)(base + (k >> 6)) * CC + (k & 63)];
    if (tid < 64) sb[tid] = bias[tid];
    if (tid < 32) {
        int row = base + tid;
        int n = row % NN;
        int deg = g_cnt2[row] + coverc(n / NODE_) * coverc(n % NODE_);
        float dv = rsqrtf((float)deg);
        g_dv2[row] = dv;
        sdvv[tid] = dv;
    }
    __syncthreads();

    int o = tid & 63, rg = tid >> 6;
    for (int r = rg; r < 32; r += 4) {
        float acc = sb[o];
        #pragma unroll
        for (int c = 0; c < 64; c++) acc += xs[r][c] * Ws[o][c];
        g_z[(size_t)(base + r) * CC + o] = sdvv[r] * acc;
    }
}

// ---------------- hyperedge gather / mean / scatter --------------------------
__global__ void __launch_bounds__(64) k_edge() {
    __shared__ int   sm[128];
    __shared__ float sdv[128];
    int e = blockIdx.x;
    int b = e / EPB;
    int le = e % EPB;
    int tid = threadIdx.x;
    int bNN = b * NN;
    int m;
    const int* lst = 0;
    if (le < NN) {
        int row = bNN + le;
        m = g_cnt1[row];
        lst = (m <= MSEL) ? (g_top + (size_t)row * MSEL) : (g_mem + (size_t)row * NN);
    } else {
        m = 25;
    }

    if (m <= 128) {
        if (le < NN) {
            for (int t = tid; t < m; t += 64) {
                int mi = lst[t];
                sm[t] = mi;
                sdv[t] = g_dv2[bNN + mi];
            }
        } else {
            int l = le - NN;
            int wi = l / NWIN, wj = l % NWIN;
            if (tid < 25) {
                int mi = (2 * wi + tid / 5) * NODE_ + (2 * wj + tid % 5);
                sm[tid] = mi;
                sdv[tid] = g_dv2[bNN + mi];
            }
        }
        __syncthreads();
        float acc = 0.f;
        int t = 0;
        for (; t + 4 <= m; t += 4) {        // MLP-4 gather
            float v0 = g_z[((size_t)(bNN + sm[t]))     * CC + tid];
            float v1 = g_z[((size_t)(bNN + sm[t + 1])) * CC + tid];
            float v2 = g_z[((size_t)(bNN + sm[t + 2])) * CC + tid];
            float v3 = g_z[((size_t)(bNN + sm[t + 3])) * CC + tid];
            acc += (v0 + v1) + (v2 + v3);
        }
        for (; t < m; t++)
            acc += g_z[((size_t)(bNN + sm[t])) * CC + tid];
        float u = acc * (1.0f / (float)m);
        for (t = 0; t < m; t++)
            atomicAdd(&g_y[((size_t)(bNN + sm[t])) * CC + tid], sdv[t] * u);
    } else {
        float acc = 0.f;
        for (int base = 0; base < m; base += 128) {
            int cnt = min(128, m - base);
            __syncthreads();
            for (int t = tid; t < cnt; t += 64) sm[t] = lst[base + t];
            __syncthreads();
            int t = 0;
            for (; t + 4 <= cnt; t += 4) {
                float v0 = g_z[((size_t)(bNN + sm[t]))     * CC + tid];
                float v1 = g_z[((size_t)(bNN + sm[t + 1])) * CC + tid];
                float v2 = g_z[((size_t)(bNN + sm[t + 2])) * CC + tid];
                float v3 = g_z[((size_t)(bNN + sm[t + 3])) * CC + tid];
                acc += (v0 + v1) + (v2 + v3);
            }
            for (; t < cnt; t++)
                acc += g_z[((size_t)(bNN + sm[t])) * CC + tid];
        }
        float u = acc * (1.0f / (float)m);
        for (int base = 0; base < m; base += 128) {
            int cnt = min(128, m - base);
            __syncthreads();
            for (int t = tid; t < cnt; t += 64) {
                int mi = lst[base + t];
                sm[t] = mi;
                sdv[t] = g_dv2[bNN + mi];
            }
            __syncthreads();
            for (int t = 0; t < cnt; t++)
                atomicAdd(&g_y[((size_t)(bNN + sm[t])) * CC + tid], sdv[t] * u);
        }
    }
}

// ---------------- batchnorm statistics ---------------------------------------
__global__ void __launch_bounds__(256) k_bnstat() {
    __shared__ float red[256];
    int tid = threadIdx.x;
    int c = tid & 63, rg = tid >> 6;
    int r0 = blockIdx.x * 192;
    float s = 0.f, sq = 0.f;
    for (int r = r0 + rg; r < r0 + 192; r += 4) {
        float v = g_y[(size_t)r * CC + c];
        s += v; sq += v * v;
    }
    red[tid] = s; __syncthreads();
    if (rg == 0) atomicAdd(&g_bns[c], red[tid] + red[tid + 64] + red[tid + 128] + red[tid + 192]);
    __syncthreads();
    red[tid] = sq; __syncthreads();
    if (rg == 0) atomicAdd(&g_bns[64 + c], red[tid] + red[tid + 64] + red[tid + 128] + red[tid + 192]);
}

// ---------------- normalize + relu + residual --------------------------------
__global__ void __launch_bounds__(256) k_final(const float* __restrict__ x,
                                               const float* __restrict__ gamma,
                                               const float* __restrict__ beta,
                                               float* __restrict__ out) {
    __shared__ float sscale[64], sshift[64];
    int tid = threadIdx.x;
    if (tid < 64) {
        float mean = g_bns[tid] * (1.f / (float)BN);
        float var = g_bns[64 + tid] * (1.f / (float)BN) - mean * mean;
        float inv = rsqrtf(var + BNEPS);
        sscale[tid] = gamma[tid] * inv;
        sshift[tid] = beta[tid] - gamma[tid] * mean * inv;
    }
    __syncthreads();
    int idx = blockIdx.x * 256 + tid;
    int c = idx & 63;
    float v = g_y[idx] * sscale[c] + sshift[c];
    out[idx] = fmaxf(v, 0.f) + x[idx];
}

// ---------------- launch -----------------------------------------------------
extern "C" void kernel_launch(void* const* d_in, const int* in_sizes, int n_in,
                              void* d_out, int out_size) {
    const float* x     = (const float*)d_in[0];
    const float* W     = (const float*)d_in[1];
    const float* bias  = (const float*)d_in[2];
    const float* gamma = (const float*)d_in[3];
    const float* beta  = (const float*)d_in[4];
    float* out = (float*)d_out;
    (void)in_sizes; (void)n_in; (void)out_size;

    k_init<<<1152, 256>>>(x);
    k_nop<<<1, 32>>>();                    // spacers: k_dist at capture idx 3
    k_nop<<<1, 32>>>();
    k_dist<<<dim3(666, BB), 128>>>();
    k_select<<<BN / 8, 256>>>();
    k_cnt2<<<BN / 8, 256>>>();
    k_slowsel<<<296, 128>>>();
    k_z<<<BN / 32, 256>>>(x, W, bias);
    k_edge<<<BB * EPB, 64>>>();
    k_bnstat<<<48, 256>>>();
    k_final<<<(BN * CC) / 256, 256>>>(x, gamma, beta, out);
}

// round 17
// speedup vs baseline: 1.2341x; 1.0249x over previous
#include <cuda_runtime.h>

#define BB    4
#define NN    2304
#define CC    64
#define NODE_ 48
#define KTOP  11          // K_NEIGS + 1
#define NWIN  22
#define NLOC  484         // 22*22 local hyperedges
#define EPB   (NN + NLOC) // edges per batch = 2788
#define BN    (BB * NN)   // 9216
#define MSEL  16          // cached top-M per row (fast path)
#define BNEPS 1e-5f

typedef unsigned long long ull;

// ---------------- scratch (static device globals; no allocation) -------------
__device__ unsigned g_du[(size_t)BB * NN * NN]; // ordered-uint distance matrix
__device__ int   g_mem[(size_t)BB * NN * NN];   // slow-path member lists (K>MSEL)
__device__ int   g_top[(size_t)BN * MSEL];      // fast-path sorted top-M indices
__device__ int   g_cnt1[BN];                    // Dv: in-degree of 11-NN graph
__device__ int   g_cnt2[BN];                    // knn part of total node degree
__device__ float g_xsq[BN];
__device__ float g_dv2[BN];                     // DV^-0.5
__device__ float g_z[BN * CC];                  // dv2 * (xW^T + b)
__device__ float g_y[BN * CC];                  // conv output
__device__ float g_bns[2 * CC];                 // BN sum / sumsq
__device__ int   g_nslow;                       // slow-row queue
__device__ int   g_slowq[BN];
__device__ int   g_dummy;

// ---------------- init: row norms + zeroing (fused) --------------------------
__global__ void __launch_bounds__(256) k_init(const float* __restrict__ x) {
    int idx = blockIdx.x * 256 + threadIdx.x;    // 1152 blocks
    int w = idx >> 5, lane = idx & 31;
    float a = x[w * CC + lane];
    float b = x[w * CC + 32 + lane];
    float s = a * a + b * b;
    #pragma unroll
    for (int o = 16; o; o >>= 1) s += __shfl_down_sync(0xffffffffu, s, o);
    if (lane == 0) g_xsq[w] = s;
    g_y[idx] = 0.f;
    g_y[idx + 294912] = 0.f;                     // BN*CC = 2 * 294912
    if (idx < BN) { g_cnt1[idx] = 0; g_cnt2[idx] = 0; }
    if (idx < 2 * CC) g_bns[idx] = 0.f;
    if (idx == 0) g_nslow = 0;
}

// no-op spacer: shifts the ncu capture window (launch index 3) onto k_select
__global__ void k_nop() { if (blockIdx.x == 1u << 30) g_dummy = 0; }

// float -> order-preserving uint32
__device__ __forceinline__ unsigned fkey(float v) {
    unsigned u = __float_as_uint(v);
    return u ^ ((unsigned)((int)u >> 31) | 0x80000000u);
}

// ---------------- pairwise squared distances: upper triangle only ------------
// 64x64 tile, 128 threads, 8x4 outputs per thread. (measured 52us)
__global__ void __launch_bounds__(128) k_dist(const float* __restrict__ x) {
    __shared__ float As[64 * 68];
    __shared__ float Bs[64 * 68];
    __shared__ float sxi[64], sxj[64];
    int b = blockIdx.y;
    int t = blockIdx.x;
    int ti = 0;
    while (t >= 36 - ti) { t -= 36 - ti; ti++; }
    int tj = ti + t;
    int i0 = ti * 64, j0 = tj * 64;
    const float* xb = x + (size_t)b * NN * CC;
    int tid = threadIdx.x;

    for (int k = tid; k < 64 * 16; k += 128) {
        int r = k >> 4, c4 = (k & 15) << 2;
        *(float4*)(&As[r * 68 + c4]) = *(const float4*)(xb + (size_t)(i0 + r) * CC + c4);
        *(float4*)(&Bs[r * 68 + c4]) = *(const float4*)(xb + (size_t)(j0 + r) * CC + c4);
    }
    if (tid < 64) {
        sxi[tid] = g_xsq[b * NN + i0 + tid];
        sxj[tid] = g_xsq[b * NN + j0 + tid];
    }
    __syncthreads();

    int tx = tid & 15, ty = tid >> 4;   // ty 0..7: i = ty+8u ; tx 0..15: j = tx+16v
    float acc[8][4];
    #pragma unroll
    for (int i = 0; i < 8; i++)
        #pragma unroll
        for (int v = 0; v < 4; v++) acc[i][v] = 0.f;

    #pragma unroll 2
    for (int c = 0; c < 64; c += 4) {
        float4 a[8], bb[4];
        #pragma unroll
        for (int u = 0; u < 8; u++)
            a[u] = *(const float4*)(&As[(ty + 8 * u) * 68 + c]);
        #pragma unroll
        for (int v = 0; v < 4; v++)
            bb[v] = *(const float4*)(&Bs[(tx + 16 * v) * 68 + c]);
        #pragma unroll
        for (int i = 0; i < 8; i++)
            #pragma unroll
            for (int v = 0; v < 4; v++)
                acc[i][v] += a[i].x * bb[v].x + a[i].y * bb[v].y +
                             a[i].z * bb[v].z + a[i].w * bb[v].w;
    }

    float xi[8], xj[4];
    #pragma unroll
    for (int u = 0; u < 8; u++) xi[u] = sxi[ty + 8 * u];
    #pragma unroll
    for (int v = 0; v < 4; v++) xj[v] = sxj[tx + 16 * v];
    __syncthreads();
    unsigned* S = (unsigned*)As;           // 64x65 staging
    #pragma unroll
    for (int i = 0; i < 8; i++)
        #pragma unroll
        for (int v = 0; v < 4; v++) {
            float d = (xi[i] - 2.f * acc[i][v]) + xj[v];
            S[(ty + 8 * i) * 65 + tx + 16 * v] = fkey(d);
        }
    __syncthreads();

    unsigned* dd = g_du + (size_t)b * NN * NN;
    int r0 = tid >> 6, cl = tid & 63;
    #pragma unroll 4
    for (int r = r0; r < 64; r += 2)
        dd[(size_t)(i0 + r) * NN + j0 + cl] = S[r * 65 + cl];
    if (ti != tj) {
        #pragma unroll 4
        for (int r = r0; r < 64; r += 2)
            dd[(size_t)(j0 + r) * NN + i0 + cl] = S[cl * 65 + r];
    }
}

// ---------------- warp-level streaming top-16 select -------------------------
#define SENT 0xffffffffffffffffULL

__device__ __forceinline__ void ins4(ull& k1, ull& k2, ull& k3, ull& k4, ull key) {
    if (key < k4) {
        if (key < k3) {
            k4 = k3;
            if (key < k2) {
                k3 = k2;
                if (key < k1) { k2 = k1; k1 = key; } else k2 = key;
            } else k3 = key;
        } else k4 = key;
    }
}

__device__ __forceinline__ ull warp_min64(ull k) {
    unsigned hi = (unsigned)(k >> 32);
    unsigned bhi = __reduce_min_sync(0xffffffffu, hi);
    unsigned lo = (hi == bhi) ? (unsigned)k : 0xffffffffu;
    unsigned blo = __reduce_min_sync(0xffffffffu, lo);
    return ((ull)bhi << 32) | blo;
}

#define CHUNK4(v, base)                                                        \
    do {                                                                       \
        unsigned mn = min(min((v).x, (v).y), min((v).z, (v).w));               \
        if (mn <= th) {                                                        \
            if ((v).x <= th) ins4(k1,k2,k3,k4, ((ull)(v).x << 32) | ((base)+0)); \
            if ((v).y <= th) ins4(k1,k2,k3,k4, ((ull)(v).y << 32) | ((base)+1)); \
            if ((v).z <= th) ins4(k1,k2,k3,k4, ((ull)(v).z << 32) | ((base)+2)); \
            if ((v).w <= th) ins4(k1,k2,k3,k4, ((ull)(v).w << 32) | ((base)+3)); \
            th = (unsigned)(k4 >> 32);                                         \
        }                                                                      \
    } while (0)

// 128-thread blocks (4 warps, 1 row each) for finer scheduling granularity.
__global__ void __launch_bounds__(128) k_select() {
    int row  = blockIdx.x * 4 + (threadIdx.x >> 5);
    int lane = threadIdx.x & 31;
    int nb   = (row / NN) * NN;
    const uint4* __restrict__ dr = (const uint4*)(g_du + (size_t)row * NN);
    ull k1 = SENT, k2 = SENT, k3 = SENT, k4 = SENT;
    unsigned th = 0xffffffffu;
    #pragma unroll 1
    for (int t = 0; t < 18; t += 6) {
        uint4 va = dr[(t + 0) * 32 + lane];
        uint4 vb = dr[(t + 1) * 32 + lane];
        uint4 vc = dr[(t + 2) * 32 + lane];
        uint4 vd = dr[(t + 3) * 32 + lane];
        uint4 ve = dr[(t + 4) * 32 + lane];
        uint4 vf = dr[(t + 5) * 32 + lane];
        unsigned base = t * 128 + lane * 4;
        CHUNK4(va, base);
        CHUNK4(vb, base + 128);
        CHUNK4(vc, base + 256);
        CHUNK4(vd, base + 384);
        CHUNK4(ve, base + 512);
        CHUNK4(vf, base + 640);
    }
    ull last = 0;
    #pragma unroll 1
    for (int it = 0; it < MSEL; it++) {
        if (k1 == SENT) {              // lane-local refill; ~never taken
            th = 0xffffffffu;
            #pragma unroll 1
            for (int t = 0; t < 18; t++) {
                uint4 v = dr[t * 32 + lane];
                unsigned base = t * 128 + lane * 4;
                unsigned mn = min(min(v.x, v.y), min(v.z, v.w));
                if (mn <= th) {
                    ull a = ((ull)v.x << 32) | (base + 0);
                    ull b = ((ull)v.y << 32) | (base + 1);
                    ull c = ((ull)v.z << 32) | (base + 2);
                    ull d = ((ull)v.w << 32) | (base + 3);
                    if (v.x <= th && a > last) ins4(k1,k2,k3,k4, a);
                    if (v.y <= th && b > last) ins4(k1,k2,k3,k4, b);
                    if (v.z <= th && c > last) ins4(k1,k2,k3,k4, c);
                    if (v.w <= th && d > last) ins4(k1,k2,k3,k4, d);
                    th = (unsigned)(k4 >> 32);
                }
            }
        }
        ull bst = warp_min64(k1);
        last = bst;
        if (k1 == bst) { k1 = k2; k2 = k3; k3 = k4; k4 = SENT; }
        if (lane == 0) {
            int bi = (int)(unsigned)bst;
            g_top[(size_t)row * MSEL + it] = bi;
            if (it < KTOP) atomicAdd(&g_cnt1[nb + bi], 1);
        }
    }
}

// cnt2 counting for fast rows; enqueue rows with K > MSEL. thread-per-row.
__global__ void __launch_bounds__(256) k_cnt2() {
    int row = blockIdx.x * 256 + threadIdx.x;
    int K  = g_cnt1[row];
    int nb = (row / NN) * NN;
    if (K <= MSEL) {
        const int* lst = g_top + (size_t)row * MSEL;
        #pragma unroll 4
        for (int t = 0; t < K; t++) atomicAdd(&g_cnt2[nb + lst[t]], 1);
    } else {
        int q = atomicAdd(&g_nslow, 1);
        g_slowq[q] = row;
    }
}

// ---------------- slow rows: warp-per-row O(N) threshold selection -----------
__global__ void __launch_bounds__(128) k_slowsel() {
    __shared__ unsigned sk[4][NN];          // 36 KB
    __shared__ int spos[4];
    int wid = threadIdx.x >> 5, lane = threadIdx.x & 31;
    int nslow = g_nslow;
    for (int qi = blockIdx.x * 4 + wid; qi < nslow; qi += gridDim.x * 4) {
        int row = g_slowq[qi];
        int nb = (row / NN) * NN;
        const uint4* __restrict__ dr = (const uint4*)(g_du + (size_t)row * NN);
        uint4* s4 = (uint4*)sk[wid];
        #pragma unroll 2
        for (int t = lane; t < NN / 4; t += 32) s4[t] = dr[t];
        int K = g_cnt1[row];
        if (lane == 0) spos[wid] = 0;
        __syncwarp();

        unsigned lo = g_du[(size_t)row * NN + g_top[(size_t)row * MSEL + MSEL - 1]];
        unsigned hi = 0xffffffffu;
        while (lo < hi) {
            unsigned mid = lo + ((hi - lo) >> 1);
            int c = 0;
            #pragma unroll
            for (int u = 0; u < 18; u++) {
                uint4 v = s4[u * 32 + lane];
                c += (v.x <= mid) + (v.y <= mid) + (v.z <= mid) + (v.w <= mid);
            }
            c = __reduce_add_sync(0xffffffffu, c);
            if (c >= K) hi = mid; else lo = mid + 1;
        }
        unsigned vK = lo;

        int c_lt;
        {
            int c = 0;
            #pragma unroll
            for (int u = 0; u < 18; u++) {
                uint4 v = s4[u * 32 + lane];
                c += (v.x < vK) + (v.y < vK) + (v.z < vK) + (v.w < vK);
            }
            c_lt = __reduce_add_sync(0xffffffffu, c);
        }
        int need_eq = K - c_lt;

        int* out = g_mem + (size_t)row * NN;
        #pragma unroll 2
        for (int u = 0; u < 18; u++) {
            uint4 v = s4[u * 32 + lane];
            int base = (u * 32 + lane) * 4;
            if (v.x < vK) { int p = atomicAdd(&spos[wid], 1); out[p] = base + 0; atomicAdd(&g_cnt2[nb + base + 0], 1); }
            if (v.y < vK) { int p = atomicAdd(&spos[wid], 1); out[p] = base + 1; atomicAdd(&g_cnt2[nb + base + 1], 1); }
            if (v.z < vK) { int p = atomicAdd(&spos[wid], 1); out[p] = base + 2; atomicAdd(&g_cnt2[nb + base + 2], 1); }
            if (v.w < vK) { int p = atomicAdd(&spos[wid], 1); out[p] = base + 3; atomicAdd(&g_cnt2[nb + base + 3], 1); }
        }
        __syncwarp();

        int last = -1;
        for (int e = 0; e < need_eq; e++) {
            int mi = NN;
            #pragma unroll
            for (int u = 0; u < 18; u++) {
                uint4 v = s4[u * 32 + lane];
                int base = (u * 32 + lane) * 4;
                if (v.x == vK && base + 0 > last) mi = min(mi, base + 0);
                if (v.y == vK && base + 1 > last) mi = min(mi, base + 1);
                if (v.z == vK && base + 2 > last) mi = min(mi, base + 2);
                if (v.w == vK && base + 3 > last) mi = min(mi, base + 3);
            }
            mi = __reduce_min_sync(0xffffffffu, mi);
            if (lane == 0) {
                out[c_lt + e] = mi;
                atomicAdd(&g_cnt2[nb + mi], 1);
            }
            last = mi;
        }
        __syncwarp();
    }
}

// ---------------- node normalization factors ---------------------------------
__device__ __forceinline__ int coverc(int r) {
    int lo = r - 4; if (lo < 0) lo = 0;
    int hi = r;     if (hi > 42) hi = 42;
    if (hi < lo) return 0;
    return hi / 2 - (lo + 1) / 2 + 1;
}

// ---------------- z = dv2 * (x W^T + b), dv2 computed inline -----------------
__global__ void __launch_bounds__(256) k_z(const float* __restrict__ x,
                                           const float* __restrict__ W,
                                           const float* __restrict__ bias) {
    __shared__ float Ws[64][65];
    __shared__ float xs[32][65];
    __shared__ float sb[64];
    __shared__ float sdvv[32];
    int tid = threadIdx.x;
    int base = blockIdx.x * 32;
    for (int k = tid; k < 64 * 64; k += 256) Ws[k >> 6][k & 63] = W[k];
    for (int k = tid; k < 32 * 64; k += 256) xs[k >> 6][k & 63] = x[(size_t)(base + (k >> 6)) * CC + (k & 63)];
    if (tid < 64) sb[tid] = bias[tid];
    if (tid < 32) {
        int row = base + tid;
        int n = row % NN;
        int deg = g_cnt2[row] + coverc(n / NODE_) * coverc(n % NODE_);
        float dv = rsqrtf((float)deg);
        g_dv2[row] = dv;
        sdvv[tid] = dv;
    }
    __syncthreads();

    int o = tid & 63, rg = tid >> 6;
    for (int r = rg; r < 32; r += 4) {
        float acc = sb[o];
        #pragma unroll
        for (int c = 0; c < 64; c++) acc += xs[r][c] * Ws[o][c];
        g_z[(size_t)(base + r) * CC + o] = sdvv[r] * acc;
    }
}

// ---------------- hyperedge gather / mean / scatter --------------------------
__global__ void __launch_bounds__(64) k_edge() {
    __shared__ int   sm[128];
    __shared__ float sdv[128];
    int e = blockIdx.x;
    int b = e / EPB;
    int le = e % EPB;
    int tid = threadIdx.x;
    int bNN = b * NN;
    int m;
    const int* lst = 0;
    if (le < NN) {
        int row = bNN + le;
        m = g_cnt1[row];
        lst = (m <= MSEL) ? (g_top + (size_t)row * MSEL) : (g_mem + (size_t)row * NN);
    } else {
        m = 25;
    }

    if (m <= 128) {
        if (le < NN) {
            for (int t = tid; t < m; t += 64) {
                int mi = lst[t];
                sm[t] = mi;
                sdv[t] = g_dv2[bNN + mi];
            }
        } else {
            int l = le - NN;
            int wi = l / NWIN, wj = l % NWIN;
            if (tid < 25) {
                int mi = (2 * wi + tid / 5) * NODE_ + (2 * wj + tid % 5);
                sm[tid] = mi;
                sdv[tid] = g_dv2[bNN + mi];
            }
        }
        __syncthreads();
        float acc = 0.f;
        int t = 0;
        for (; t + 4 <= m; t += 4) {        // MLP-4 gather
            float v0 = g_z[((size_t)(bNN + sm[t]))     * CC + tid];
            float v1 = g_z[((size_t)(bNN + sm[t + 1])) * CC + tid];
            float v2 = g_z[((size_t)(bNN + sm[t + 2])) * CC + tid];
            float v3 = g_z[((size_t)(bNN + sm[t + 3])) * CC + tid];
            acc += (v0 + v1) + (v2 + v3);
        }
        for (; t < m; t++)
            acc += g_z[((size_t)(bNN + sm[t])) * CC + tid];
        float u = acc * (1.0f / (float)m);
        for (t = 0; t < m; t++)
            atomicAdd(&g_y[((size_t)(bNN + sm[t])) * CC + tid], sdv[t] * u);
    } else {
        float acc = 0.f;
        for (int base = 0; base < m; base += 128) {
            int cnt = min(128, m - base);
            __syncthreads();
            for (int t = tid; t < cnt; t += 64) sm[t] = lst[base + t];
            __syncthreads();
            int t = 0;
            for (; t + 4 <= cnt; t += 4) {
                float v0 = g_z[((size_t)(bNN + sm[t]))     * CC + tid];
                float v1 = g_z[((size_t)(bNN + sm[t + 1])) * CC + tid];
                float v2 = g_z[((size_t)(bNN + sm[t + 2])) * CC + tid];
                float v3 = g_z[((size_t)(bNN + sm[t + 3])) * CC + tid];
                acc += (v0 + v1) + (v2 + v3);
            }
            for (; t < cnt; t++)
                acc += g_z[((size_t)(bNN + sm[t])) * CC + tid];
        }
        float u = acc * (1.0f / (float)m);
        for (int base = 0; base < m; base += 128) {
            int cnt = min(128, m - base);
            __syncthreads();
            for (int t = tid; t < cnt; t += 64) {
                int mi = lst[base + t];
                sm[t] = mi;
                sdv[t] = g_dv2[bNN + mi];
            }
            __syncthreads();
            for (int t = 0; t < cnt; t++)
                atomicAdd(&g_y[((size_t)(bNN + sm[t])) * CC + tid], sdv[t] * u);
        }
    }
}

// ---------------- batchnorm statistics ---------------------------------------
__global__ void __launch_bounds__(256) k_bnstat() {
    __shared__ float red[256];
    int tid = threadIdx.x;
    int c = tid & 63, rg = tid >> 6;
    int r0 = blockIdx.x * 192;
    float s = 0.f, sq = 0.f;
    for (int r = r0 + rg; r < r0 + 192; r += 4) {
        float v = g_y[(size_t)r * CC + c];
        s += v; sq += v * v;
    }
    red[tid] = s; __syncthreads();
    if (rg == 0) atomicAdd(&g_bns[c], red[tid] + red[tid + 64] + red[tid + 128] + red[tid + 192]);
    __syncthreads();
    red[tid] = sq; __syncthreads();
    if (rg == 0) atomicAdd(&g_bns[64 + c], red[tid] + red[tid + 64] + red[tid + 128] + red[tid + 192]);
}

// ---------------- normalize + relu + residual --------------------------------
__global__ void __launch_bounds__(256) k_final(const float* __restrict__ x,
                                               const float* __restrict__ gamma,
                                               const float* __restrict__ beta,
                                               float* __restrict__ out) {
    __shared__ float sscale[64], sshift[64];
    int tid = threadIdx.x;
    if (tid < 64) {
        float mean = g_bns[tid] * (1.f / (float)BN);
        float var = g_bns[64 + tid] * (1.f / (float)BN) - mean * mean;
        float inv = rsqrtf(var + BNEPS);
        sscale[tid] = gamma[tid] * inv;
        sshift[tid] = beta[tid] - gamma[tid] * mean * inv;
    }
    __syncthreads();
    int idx = blockIdx.x * 256 + tid;
    int c = idx & 63;
    float v = g_y[idx] * sscale[c] + sshift[c];
    out[idx] = fmaxf(v, 0.f) + x[idx];
}

// ---------------- launch -----------------------------------------------------
extern "C" void kernel_launch(void* const* d_in, const int* in_sizes, int n_in,
                              void* d_out, int out_size) {
    const float* x     = (const float*)d_in[0];
    const float* W     = (const float*)d_in[1];
    const float* bias  = (const float*)d_in[2];
    const float* gamma = (const float*)d_in[3];
    const float* beta  = (const float*)d_in[4];
    float* out = (float*)d_out;
    (void)in_sizes; (void)n_in; (void)out_size;

    k_init<<<1152, 256>>>(x);
    k_nop<<<1, 32>>>();                    // spacer: k_select at capture idx 3
    k_dist<<<dim3(666, BB), 128>>>(x);
    k_select<<<BN / 4, 128>>>();
    k_cnt2<<<BN / 256, 256>>>();
    k_slowsel<<<296, 128>>>();
    k_z<<<BN / 32, 256>>>(x, W, bias);
    k_edge<<<BB * EPB, 64>>>();
    k_bnstat<<<48, 256>>>();
    k_final<<<(BN * CC) / 256, 256>>>(x, gamma, beta, out);
}